// round 15
// baseline (speedup 1.0000x reference)
#include <cuda_runtime.h>
#include <cuda_fp16.h>
#include <cstdint>
#include <math.h>

// Problem dims
#define B_  64
#define T_  512
#define F_  20
#define D_  1024
#define O_  1095
#define L_  3
#define M_  (B_ * T_)        // 32768
#define N3_ (3 * D_)         // 3072
#define OPAD 1152
#define Y_SIZE ((size_t)M_ * O_)

// ---------------------------------------------------------------------------
// Scratch (static device globals)
// ---------------------------------------------------------------------------
// Fused U granule: one 16B block per (row, channel-pair):
//   bytes [0:8)  = u0[ch0], u0[ch0+1]  (fp32)
//   bytes [8:12) = u1[ch0], u1[ch0+1]  (fp16)
//   bytes [12:16)= u2[ch0], u2[ch0+1]  (fp16)
__device__ uint4  g_U[(size_t)M_ * (D_ / 2)];     // 256 MB
__device__ __half g_A[(size_t)M_ * D_];           // fp16 hidden (time-major)
__device__ __half g_Aord[(size_t)M_ * D_];        // fp16 hidden (batch-major, last layer)
__device__ __half g_Wt[(size_t)L_ * N3_ * D_];    // sru_W^T fp16  [l][n][k]
__device__ __half g_W3t[(size_t)OPAD * D_];       // W3^T fp16 (zero padded)

__device__ __forceinline__ uint32_t smem_to_u32(const void* p) {
    uint32_t a;
    asm("{ .reg .u64 t; cvta.to.shared.u64 t, %1; cvt.u32.u64 %0, t; }" : "=r"(a) : "l"(p));
    return a;
}

// ---------------------------------------------------------------------------
// Input projection -> g_A (fp16), time-major
// ---------------------------------------------------------------------------
#define PROJ_ROWS 16
__global__ __launch_bounds__(256) void proj_kernel(
    const float* __restrict__ x, const float* __restrict__ W1,
    const float* __restrict__ b1)
{
    int r0 = blockIdx.x * PROJ_ROWS;
    __shared__ float xs[PROJ_ROWS][F_];
    for (int i = threadIdx.x; i < PROJ_ROWS * F_; i += blockDim.x) {
        int rr = i / F_, f = i % F_;
        int r = r0 + rr;
        int b = r % B_, t = r / B_;
        xs[rr][f] = x[((size_t)b * T_ + t) * F_ + f];
    }
    __syncthreads();
    for (int d = threadIdx.x; d < D_; d += blockDim.x) {
        float w[F_];
#pragma unroll
        for (int f = 0; f < F_; f++) w[f] = W1[f * D_ + d];
        float bb = b1[d];
#pragma unroll
        for (int rr = 0; rr < PROJ_ROWS; rr++) {
            float acc = bb;
#pragma unroll
            for (int f = 0; f < F_; f++) acc += xs[rr][f] * w[f];
            g_A[(size_t)(r0 + rr) * D_ + d] = __float2half(acc);
        }
    }
}

// ---------------------------------------------------------------------------
// Weight prep (merged): z<L -> sru layer z; z==L -> W3 (zero padded)
// ---------------------------------------------------------------------------
__global__ __launch_bounds__(256) void wprep_kernel(
    const float* __restrict__ W, const float* __restrict__ W3)
{
    __shared__ float tile[32][33];
    int z = blockIdx.z;
    int n0 = blockIdx.x * 32, k0 = blockIdx.y * 32;
    int tx = threadIdx.x & 31, ty = threadIdx.x >> 5;

    if (z < L_) {
        const float* Wl = W + (size_t)z * D_ * N3_;
        for (int dy = ty; dy < 32; dy += 8)
            tile[dy][tx] = Wl[(size_t)(k0 + dy) * N3_ + n0 + tx];
        __syncthreads();
        __half* oh = g_Wt + (size_t)z * N3_ * D_;
        for (int dy = ty; dy < 32; dy += 8)
            oh[(size_t)(n0 + dy) * D_ + k0 + tx] = __float2half(tile[tx][dy]);
    } else {
        if (n0 >= OPAD) return;
        for (int dy = ty; dy < 32; dy += 8) {
            int n = n0 + tx;
            tile[dy][tx] = (n < O_) ? W3[(size_t)(k0 + dy) * O_ + n] : 0.0f;
        }
        __syncthreads();
        for (int dy = ty; dy < 32; dy += 8)
            g_W3t[(size_t)(n0 + dy) * D_ + k0 + tx] = __float2half(tile[tx][dy]);
    }
}

// ---------------------------------------------------------------------------
// mma.sync fp16 GEMM. BK=64, 3-stage cp.async pipeline, ONE sync per k-iter.
// SRU mode (Upk != null): writes into fused 16B U granules:
//   col<1024: u0 pair -> float2 at block+0
//   col in [1024,2048): u1 pair -> half2 at block+8
//   col in [2048,3072): u2 pair -> half2 at block+12
// ---------------------------------------------------------------------------
#define BKK 64
#define NCHUNK (D_ / BKK)        // 16
#define TILE_B (128 * 128)       // 16384 bytes per tile
#define STAGE_B (2 * TILE_B)     // 32768 (A + B)
#define GEMM_SMEM (3 * STAGE_B)  // 98304
#define UROW_B (D_ / 2 * 16)     // 8192 bytes per U row

#define CP_ASYNC16(s, g) \
    asm volatile("cp.async.cg.shared.global [%0], [%1], 16;" :: "r"(s), "l"(g))
#define CP_ASYNC8(s, g) \
    asm volatile("cp.async.ca.shared.global [%0], [%1], 8;" :: "r"(s), "l"(g))
#define CP_ASYNC4(s, g) \
    asm volatile("cp.async.ca.shared.global [%0], [%1], 4;" :: "r"(s), "l"(g))
#define CP_COMMIT() asm volatile("cp.async.commit_group;" ::: "memory")
#define CP_WAIT(n)  asm volatile("cp.async.wait_group %0;" :: "n"(n) : "memory")

#define LDSM_X4(r0, r1, r2, r3, a) \
    asm volatile("ldmatrix.sync.aligned.m8n8.x4.shared.b16 {%0,%1,%2,%3}, [%4];" \
        : "=r"(r0), "=r"(r1), "=r"(r2), "=r"(r3) : "r"(a))

#define MMA16816(c, a, b) \
    asm volatile("mma.sync.aligned.m16n8k16.row.col.f32.f16.f16.f32 " \
        "{%0,%1,%2,%3}, {%4,%5,%6,%7}, {%8,%9}, {%0,%1,%2,%3};" \
        : "+f"((c)[0]), "+f"((c)[1]), "+f"((c)[2]), "+f"((c)[3]) \
        : "r"((a)[0]), "r"((a)[1]), "r"((a)[2]), "r"((a)[3]), "r"((b)[0]), "r"((b)[1]))

__device__ __forceinline__ void load_tile(uint32_t sbase, const __half* g,
                                          int row0, int kk) {
    const int tid = threadIdx.x;
#pragma unroll
    for (int j = 0; j < 4; j++) {
        int i = tid + 256 * j;         // 0..1023
        int row = i >> 3;
        int c = i & 7;
        uint32_t s = sbase + row * 128 + ((c ^ (row & 7)) << 4);
        const void* gp = g + (size_t)(row0 + row) * D_ + kk + c * 8;
        CP_ASYNC16(s, gp);
    }
}

__global__ __launch_bounds__(256, 2) void gemm_kernel(
    const __half* __restrict__ A, const __half* __restrict__ Bm,
    float* __restrict__ C, int ldc, int nmax, const float* __restrict__ bias,
    uint4* __restrict__ Upk)
{
    extern __shared__ char smem[];
    const uint32_t sbase = smem_to_u32(smem);
    const int tid = threadIdx.x;
    const int lane = tid & 31;
    const int wid = tid >> 5;
    const int wm = wid & 3;
    const int wn = wid >> 2;
    const int m0 = blockIdx.y * 128;
    const int n0 = blockIdx.x * 128;

    float acc[2][8][4];
#pragma unroll
    for (int i = 0; i < 2; i++)
#pragma unroll
        for (int j = 0; j < 8; j++)
#pragma unroll
            for (int q = 0; q < 4; q++) acc[i][j][q] = 0.0f;

#pragma unroll
    for (int p = 0; p < 2; p++) {
        uint32_t st = sbase + p * STAGE_B;
        load_tile(st + 0 * TILE_B, A, m0, p * BKK);
        load_tile(st + 1 * TILE_B, Bm, n0, p * BKK);
        CP_COMMIT();
    }

    const int a_roff = (lane & 7) + ((lane >> 3) & 1) * 8;
    const int a_half = (lane >> 4) & 1;
    const int b_roff = (lane & 7) + ((lane >> 4) & 1) * 8;
    const int b_half = (lane >> 3) & 1;

    int stage = 0;
    for (int k = 0; k < NCHUNK; k++) {
        if (k < NCHUNK - 1) CP_WAIT(1); else CP_WAIT(0);
        __syncthreads();

        const uint32_t st = sbase + stage * STAGE_B;
        const uint32_t aA = st, aB = st + TILE_B;

#pragma unroll
        for (int ks = 0; ks < 4; ks++) {
            uint32_t af[2][4], bf[8][2];
#pragma unroll
            for (int mi = 0; mi < 2; mi++) {
                int row = wm * 32 + mi * 16 + a_roff;
                int c = (ks * 2 + a_half) ^ (row & 7);
                LDSM_X4(af[mi][0], af[mi][1], af[mi][2], af[mi][3],
                        aA + row * 128 + (c << 4));
            }
#pragma unroll
            for (int g = 0; g < 4; g++) {
                int row = wn * 64 + g * 16 + b_roff;
                int c = (ks * 2 + b_half) ^ (row & 7);
                uint32_t r0, r1, r2, r3;
                LDSM_X4(r0, r1, r2, r3, aB + row * 128 + (c << 4));
                bf[g * 2][0] = r0; bf[g * 2][1] = r1;
                bf[g * 2 + 1][0] = r2; bf[g * 2 + 1][1] = r3;
            }
#pragma unroll
            for (int mi = 0; mi < 2; mi++)
#pragma unroll
                for (int ni = 0; ni < 8; ni++)
                    MMA16816(acc[mi][ni], af[mi], bf[ni]);
        }

        if (k + 2 < NCHUNK) {
            int s2 = stage + 2; if (s2 >= 3) s2 -= 3;
            uint32_t stw = sbase + s2 * STAGE_B;
            const int kk = (k + 2) * BKK;
            load_tile(stw + 0 * TILE_B, A, m0, kk);
            load_tile(stw + 1 * TILE_B, Bm, n0, kk);
        }
        CP_COMMIT();
        if (++stage == 3) stage = 0;
    }

    // ----- epilogue -----
    if (Upk) {
#pragma unroll
        for (int ni = 0; ni < 8; ni++) {
            int col = n0 + wn * 64 + ni * 8 + (lane & 3) * 2;   // even
#pragma unroll
            for (int mi = 0; mi < 2; mi++) {
                int row = m0 + wm * 32 + mi * 16 + (lane >> 2);
                char* r0 = (char*)Upk + (size_t)row * UROW_B;
                char* r1 = (char*)Upk + (size_t)(row + 8) * UROW_B;
                if (col < D_) {
                    int blk = (col >> 1) * 16;
                    *(float2*)(r0 + blk) = make_float2(acc[mi][ni][0], acc[mi][ni][1]);
                    *(float2*)(r1 + blk) = make_float2(acc[mi][ni][2], acc[mi][ni][3]);
                } else if (col < 2 * D_) {
                    int blk = ((col - D_) >> 1) * 16 + 8;
                    *(__half2*)(r0 + blk) = __floats2half2_rn(acc[mi][ni][0], acc[mi][ni][1]);
                    *(__half2*)(r1 + blk) = __floats2half2_rn(acc[mi][ni][2], acc[mi][ni][3]);
                } else {
                    int blk = ((col - 2 * D_) >> 1) * 16 + 12;
                    *(__half2*)(r0 + blk) = __floats2half2_rn(acc[mi][ni][0], acc[mi][ni][1]);
                    *(__half2*)(r1 + blk) = __floats2half2_rn(acc[mi][ni][2], acc[mi][ni][3]);
                }
            }
        }
    } else {
        const bool vec = ((ldc & 1) == 0);
#pragma unroll
        for (int ni = 0; ni < 8; ni++) {
            int col = n0 + wn * 64 + ni * 8 + (lane & 3) * 2;
            float bv0 = 0.f, bv1 = 0.f;
            if (bias) {
                if (col < nmax)     bv0 = bias[col];
                if (col + 1 < nmax) bv1 = bias[col + 1];
            }
#pragma unroll
            for (int mi = 0; mi < 2; mi++) {
                int row = m0 + wm * 32 + mi * 16 + (lane >> 2);
                float* p0 = C + (size_t)row * ldc + col;
                float* p1 = C + (size_t)(row + 8) * ldc + col;
                if (vec && col + 1 < nmax) {
                    *(float2*)p0 = make_float2(acc[mi][ni][0] + bv0, acc[mi][ni][1] + bv1);
                    *(float2*)p1 = make_float2(acc[mi][ni][2] + bv0, acc[mi][ni][3] + bv1);
                } else {
                    if (col < nmax) {
                        p0[0] = acc[mi][ni][0] + bv0;
                        p1[0] = acc[mi][ni][2] + bv0;
                    }
                    if (col + 1 < nmax) {
                        p0[1] = acc[mi][ni][1] + bv1;
                        p1[1] = acc[mi][ni][3] + bv1;
                    }
                }
            }
        }
    }
}

// ---------------------------------------------------------------------------
// SRU recurrence: ONE channel per thread, cp.async SMEM ring of depth 8.
// Per timestep: ONE CP_ASYNC16 (fused u0/u1/u2 granule) + ONE CP_ASYNC4 (xt),
// one LDS.128 + one LDS.32. t-loop unrolled by 8, pointer-increment streams.
// 128 CTAs x 512 threads. Dynamic smem: 8 x 512 x (16+4) = 80 KB.
// ---------------------------------------------------------------------------
#define SPFD 8      // ring depth; T_ % SPFD == 0
#define STH 512     // threads per CTA -> 128 CTAs (single wave)
#define SRU_SMEM (SPFD * STH * 20)   // 81920 bytes

__global__ __launch_bounds__(STH) void sru_kernel(
    const uint4* __restrict__ Upk,
    __half* __restrict__ A, __half* __restrict__ Aord,
    const float* __restrict__ v, const float* __restrict__ bp,
    float* __restrict__ cfin, int last)
{
    extern __shared__ char ssru[];
    uint4* s_U = (uint4*)ssru;                              // [SPFD][STH] 64 KB
    uint32_t* s_xt = (uint32_t*)(ssru + SPFD * STH * 16);   // [SPFD][STH] 16 KB

    const int tid = threadIdx.x;
    int idx = blockIdx.x * STH + tid;   // 0 .. B_*D_-1 (one channel)
    int b = idx >> 10;                  // / D_
    int d = idx & (D_ - 1);
    int d0 = d & ~1;
    int sub = d & 1;

    const float vf = v[d], vr = v[D_ + d];
    const float bf = bp[d], br = bp[D_ + d];
    float c = 0.0f;

    const size_t goff  = (size_t)b * (D_ / 2) + (d >> 1);   // U granule index
    const size_t gstep = (size_t)B_ * (D_ / 2);
    const size_t xtoff = (size_t)b * D_ + d0;
    const size_t u0step = (size_t)B_ * D_;
    const size_t u0off = (size_t)b * D_ + d;

    // global stream pointers (increment each iteration)
    const uint4*  ldU  = Upk + goff + SPFD * gstep;
    const __half* ldXt = A + xtoff + SPFD * u0step;
    __half* pOut = last ? (Aord + (size_t)b * T_ * D_ + d) : (A + u0off);
    const size_t outstep = last ? (size_t)D_ : u0step;

    const uint32_t sU  = smem_to_u32(&s_U[tid]);
    const uint32_t sxt = smem_to_u32(&s_xt[tid]);

    // prologue: stage timesteps 0..SPFD-1, one commit group each
#pragma unroll
    for (int p = 0; p < SPFD; p++) {
        CP_ASYNC16(sU + p * STH * 16, Upk + goff + (size_t)p * gstep);
        CP_ASYNC4(sxt + p * STH * 4, A + xtoff + (size_t)p * u0step);
        CP_COMMIT();
    }

    for (int t0 = 0; t0 < T_; t0 += SPFD) {
#pragma unroll
        for (int j = 0; j < SPFD; j++) {
            CP_WAIT(7);   // oldest group (stage t0+j) complete

            uint4 w = s_U[j * STH + tid];
            float u0 = __uint_as_float(sub ? w.y : w.x);
            float2 u1p = __half22float2(*(__half2*)&w.z);
            float2 u2p = __half22float2(*(__half2*)&w.w);
            float u1 = sub ? u1p.y : u1p.x;
            float u2 = sub ? u2p.y : u2p.x;
            uint32_t xw = s_xt[j * STH + tid];
            float2 xp = __half22float2(*(__half2*)&xw);
            float xt = sub ? xp.y : xp.x;

            if (t0 + j + SPFD < T_) {
                CP_ASYNC16(sU + j * STH * 16, ldU);
                CP_ASYNC4(sxt + j * STH * 4, ldXt);
            }
            ldU += gstep; ldXt += u0step;
            CP_COMMIT();

            float f = 1.0f / (1.0f + __expf(-(u1 + vf * c + bf)));
            c = f * c + (1.0f - f) * u0;
            float r = 1.0f / (1.0f + __expf(-(u2 + vr * c + br)));
            float h = r * c + (1.0f - r) * xt;

            *pOut = __float2half(h);
            pOut += outstep;
        }
    }
    cfin[u0off] = c;
}

// ---------------------------------------------------------------------------
// Launcher
// ---------------------------------------------------------------------------
extern "C" void kernel_launch(void* const* d_in, const int* in_sizes, int n_in,
                              void* d_out, int out_size)
{
    const float* x     = (const float*)d_in[0];
    const float* W1    = (const float*)d_in[2];
    const float* b1    = (const float*)d_in[3];
    const float* sru_W = (const float*)d_in[4];
    const float* sru_v = (const float*)d_in[5];
    const float* sru_b = (const float*)d_in[6];
    const float* W3    = (const float*)d_in[7];
    const float* b3    = (const float*)d_in[8];
    float* out = (float*)d_out;

    uint4* UP;
    __half *AP, *AordP, *WtP, *W3tP;
    cudaGetSymbolAddress((void**)&UP, g_U);
    cudaGetSymbolAddress((void**)&AP, g_A);
    cudaGetSymbolAddress((void**)&AordP, g_Aord);
    cudaGetSymbolAddress((void**)&WtP, g_Wt);
    cudaGetSymbolAddress((void**)&W3tP, g_W3t);

    cudaFuncSetAttribute(gemm_kernel, cudaFuncAttributeMaxDynamicSharedMemorySize, GEMM_SMEM);
    cudaFuncSetAttribute(sru_kernel, cudaFuncAttributeMaxDynamicSharedMemorySize, SRU_SMEM);

    // Weight prep (merged: 3 SRU layers + W3)
    {
        dim3 g(N3_ / 32, D_ / 32, L_ + 1);
        wprep_kernel<<<g, 256>>>(sru_W, W3);
    }

    // Input projection
    proj_kernel<<<M_ / PROJ_ROWS, 256>>>(x, W1, b1);

    // SRU layers
    for (int l = 0; l < L_; l++) {
        const __half* Bh = WtP + (size_t)l * N3_ * D_;
        dim3 grid(N3_ / 128, M_ / 128);
        gemm_kernel<<<grid, 256, GEMM_SMEM>>>(AP, Bh, nullptr, 0, 0, nullptr, UP);

        const float* vl = sru_v + (size_t)l * 2 * D_;
        const float* bl = sru_b + (size_t)l * 2 * D_;
        float* cfin = out + Y_SIZE + (size_t)l * B_ * D_;
        int last = (l == L_ - 1) ? 1 : 0;
        sru_kernel<<<(B_ * D_) / STH, STH, SRU_SMEM>>>(UP, AP, AordP, vl, bl, cfin, last);
    }

    // Output GEMM: y = h @ W3 + b3
    {
        dim3 grid(OPAD / 128, M_ / 128);
        gemm_kernel<<<grid, 256, GEMM_SMEM>>>(AordP, W3tP, out, O_, O_, b3, nullptr);
    }
}

// round 16
// speedup vs baseline: 1.1666x; 1.1666x over previous
#include <cuda_runtime.h>
#include <cuda_fp16.h>
#include <cstdint>
#include <math.h>

// Problem dims
#define B_  64
#define T_  512
#define F_  20
#define D_  1024
#define O_  1095
#define L_  3
#define M_  (B_ * T_)        // 32768
#define N3_ (3 * D_)         // 3072
#define OPAD 1152
#define KP0 64               // padded K for the fused layer-0 GEMM
#define Y_SIZE ((size_t)M_ * O_)

// ---------------------------------------------------------------------------
// Scratch (static device globals)
// ---------------------------------------------------------------------------
__device__ float  g_U0[(size_t)M_ * D_];          // u0 gate pre-activation (fp32)
__device__ __half g_U12[(size_t)M_ * 2 * D_];     // pair-interleaved (R14 layout)
__device__ __half g_A[(size_t)M_ * D_];           // fp16 hidden (time-major)
__device__ __half g_Aord[(size_t)M_ * D_];        // fp16 hidden (batch-major, last layer)
__device__ __half g_Wt[(size_t)L_ * N3_ * D_];    // sru_W^T fp16  [l][n][k]
__device__ __half g_W3t[(size_t)OPAD * D_];       // W3^T fp16 (zero padded)
__device__ __half g_X16[(size_t)M_ * KP0];        // fp16 x, time-major, K padded 20->64
__device__ __half g_Weff[(size_t)N3_ * KP0];      // (W1 @ W0)^T fp16, [n][k], zero pad
__device__ float  g_beff[N3_];                    // b1 @ W0 (fp32)

__device__ __forceinline__ uint32_t smem_to_u32(const void* p) {
    uint32_t a;
    asm("{ .reg .u64 t; cvta.to.shared.u64 t, %1; cvt.u32.u64 %0, t; }" : "=r"(a) : "l"(p));
    return a;
}

// ---------------------------------------------------------------------------
// Input projection -> g_A (fp16, time-major) AND g_X16 (fp16 x rows, padded)
// ---------------------------------------------------------------------------
#define PROJ_ROWS 16
__global__ __launch_bounds__(256) void proj_kernel(
    const float* __restrict__ x, const float* __restrict__ W1,
    const float* __restrict__ b1)
{
    int r0 = blockIdx.x * PROJ_ROWS;
    __shared__ float xs[PROJ_ROWS][F_];
    for (int i = threadIdx.x; i < PROJ_ROWS * F_; i += blockDim.x) {
        int rr = i / F_, f = i % F_;
        int r = r0 + rr;
        int b = r % B_, t = r / B_;
        xs[rr][f] = x[((size_t)b * T_ + t) * F_ + f];
    }
    __syncthreads();
    // write padded fp16 x rows
    for (int i = threadIdx.x; i < PROJ_ROWS * KP0; i += blockDim.x) {
        int rr = i / KP0, f = i % KP0;
        g_X16[(size_t)(r0 + rr) * KP0 + f] =
            __float2half(f < F_ ? xs[rr][f] : 0.0f);
    }
    for (int d = threadIdx.x; d < D_; d += blockDim.x) {
        float w[F_];
#pragma unroll
        for (int f = 0; f < F_; f++) w[f] = W1[f * D_ + d];
        float bb = b1[d];
#pragma unroll
        for (int rr = 0; rr < PROJ_ROWS; rr++) {
            float acc = bb;
#pragma unroll
            for (int f = 0; f < F_; f++) acc += xs[rr][f] * w[f];
            g_A[(size_t)(r0 + rr) * D_ + d] = __float2half(acc);
        }
    }
}

// ---------------------------------------------------------------------------
// Weight prep (merged): z<L -> sru layer z; z==L -> W3 (zero padded)
// ---------------------------------------------------------------------------
__global__ __launch_bounds__(256) void wprep_kernel(
    const float* __restrict__ W, const float* __restrict__ W3)
{
    __shared__ float tile[32][33];
    int z = blockIdx.z;
    int n0 = blockIdx.x * 32, k0 = blockIdx.y * 32;
    int tx = threadIdx.x & 31, ty = threadIdx.x >> 5;

    if (z < L_) {
        const float* Wl = W + (size_t)z * D_ * N3_;
        for (int dy = ty; dy < 32; dy += 8)
            tile[dy][tx] = Wl[(size_t)(k0 + dy) * N3_ + n0 + tx];
        __syncthreads();
        __half* oh = g_Wt + (size_t)z * N3_ * D_;
        for (int dy = ty; dy < 32; dy += 8)
            oh[(size_t)(n0 + dy) * D_ + k0 + tx] = __float2half(tile[tx][dy]);
    } else {
        if (n0 >= OPAD) return;
        for (int dy = ty; dy < 32; dy += 8) {
            int n = n0 + tx;
            tile[dy][tx] = (n < O_) ? W3[(size_t)(k0 + dy) * O_ + n] : 0.0f;
        }
        __syncthreads();
        for (int dy = ty; dy < 32; dy += 8)
            g_W3t[(size_t)(n0 + dy) * D_ + k0 + tx] = __float2half(tile[tx][dy]);
    }
}

// ---------------------------------------------------------------------------
// W_eff prep: g_Weff[n][k] = sum_d W1[k][d]*W0[d][n] (via g_Wt[0] rows),
// g_beff[n] = sum_d b1[d]*W0[d][n].   One block per n, 32 threads (k=tid).
// ---------------------------------------------------------------------------
__global__ __launch_bounds__(32) void weff_kernel(
    const float* __restrict__ W1, const float* __restrict__ b1)
{
    int n = blockIdx.x;
    int k = threadIdx.x;          // 0..31
    const __half* wt0 = g_Wt + (size_t)n * D_;   // W0^T row n (fp16)
    if (k < F_) {
        const float* w1row = W1 + (size_t)k * D_;
        float acc = 0.0f;
#pragma unroll 4
        for (int d = 0; d < D_; d++)
            acc += w1row[d] * __half2float(wt0[d]);
        g_Weff[(size_t)n * KP0 + k] = __float2half(acc);
    } else if (k < KP0 && k < 32) {
        g_Weff[(size_t)n * KP0 + k] = __float2half(0.0f);
    }
    if (k == 20) {
        float acc = 0.0f;
#pragma unroll 4
        for (int d = 0; d < D_; d++)
            acc += b1[d] * __half2float(wt0[d]);
        g_beff[n] = acc;
    }
    // zero pad cols 32..63
    if (k < 32) g_Weff[(size_t)n * KP0 + 32 + k] = __float2half(0.0f);
}

// ---------------------------------------------------------------------------
// mma.sync fp16 GEMM. BK=64, 3-stage cp.async pipeline, ONE sync per k-iter.
// SRU mode (U0 != null): u0 -> fp32 U0; u1/u2 -> pair-interleaved fp16 U12.
// (R14-measured configuration — unchanged.)
// ---------------------------------------------------------------------------
#define BKK 64
#define NCHUNK (D_ / BKK)        // 16
#define TILE_B (128 * 128)       // 16384 bytes per tile
#define STAGE_B (2 * TILE_B)     // 32768 (A + B)
#define GEMM_SMEM (3 * STAGE_B)  // 98304

#define CP_ASYNC16(s, g) \
    asm volatile("cp.async.cg.shared.global [%0], [%1], 16;" :: "r"(s), "l"(g))
#define CP_ASYNC8(s, g) \
    asm volatile("cp.async.ca.shared.global [%0], [%1], 8;" :: "r"(s), "l"(g))
#define CP_ASYNC4(s, g) \
    asm volatile("cp.async.ca.shared.global [%0], [%1], 4;" :: "r"(s), "l"(g))
#define CP_COMMIT() asm volatile("cp.async.commit_group;" ::: "memory")
#define CP_WAIT(n)  asm volatile("cp.async.wait_group %0;" :: "n"(n) : "memory")

#define LDSM_X4(r0, r1, r2, r3, a) \
    asm volatile("ldmatrix.sync.aligned.m8n8.x4.shared.b16 {%0,%1,%2,%3}, [%4];" \
        : "=r"(r0), "=r"(r1), "=r"(r2), "=r"(r3) : "r"(a))

#define MMA16816(c, a, b) \
    asm volatile("mma.sync.aligned.m16n8k16.row.col.f32.f16.f16.f32 " \
        "{%0,%1,%2,%3}, {%4,%5,%6,%7}, {%8,%9}, {%0,%1,%2,%3};" \
        : "+f"((c)[0]), "+f"((c)[1]), "+f"((c)[2]), "+f"((c)[3]) \
        : "r"((a)[0]), "r"((a)[1]), "r"((a)[2]), "r"((a)[3]), "r"((b)[0]), "r"((b)[1]))

__device__ __forceinline__ void load_tile(uint32_t sbase, const __half* g,
                                          int row0, int kk) {
    const int tid = threadIdx.x;
#pragma unroll
    for (int j = 0; j < 4; j++) {
        int i = tid + 256 * j;         // 0..1023
        int row = i >> 3;
        int c = i & 7;
        uint32_t s = sbase + row * 128 + ((c ^ (row & 7)) << 4);
        const void* gp = g + (size_t)(row0 + row) * D_ + kk + c * 8;
        CP_ASYNC16(s, gp);
    }
}

// stride-64 variant for the layer-0 fused GEMM (full row = 64 halves)
__device__ __forceinline__ void load_tile64(uint32_t sbase, const __half* g,
                                            int row0) {
    const int tid = threadIdx.x;
#pragma unroll
    for (int j = 0; j < 4; j++) {
        int i = tid + 256 * j;
        int row = i >> 3;
        int c = i & 7;
        uint32_t s = sbase + row * 128 + ((c ^ (row & 7)) << 4);
        const void* gp = g + (size_t)(row0 + row) * KP0 + c * 8;
        CP_ASYNC16(s, gp);
    }
}

__global__ __launch_bounds__(256, 2) void gemm_kernel(
    const __half* __restrict__ A, const __half* __restrict__ Bm,
    float* __restrict__ C, int ldc, int nmax, const float* __restrict__ bias,
    float* __restrict__ U0, __half* __restrict__ U12)
{
    extern __shared__ char smem[];
    const uint32_t sbase = smem_to_u32(smem);
    const int tid = threadIdx.x;
    const int lane = tid & 31;
    const int wid = tid >> 5;
    const int wm = wid & 3;
    const int wn = wid >> 2;
    const int m0 = blockIdx.y * 128;
    const int n0 = blockIdx.x * 128;

    float acc[2][8][4];
#pragma unroll
    for (int i = 0; i < 2; i++)
#pragma unroll
        for (int j = 0; j < 8; j++)
#pragma unroll
            for (int q = 0; q < 4; q++) acc[i][j][q] = 0.0f;

#pragma unroll
    for (int p = 0; p < 2; p++) {
        uint32_t st = sbase + p * STAGE_B;
        load_tile(st + 0 * TILE_B, A, m0, p * BKK);
        load_tile(st + 1 * TILE_B, Bm, n0, p * BKK);
        CP_COMMIT();
    }

    const int a_roff = (lane & 7) + ((lane >> 3) & 1) * 8;
    const int a_half = (lane >> 4) & 1;
    const int b_roff = (lane & 7) + ((lane >> 4) & 1) * 8;
    const int b_half = (lane >> 3) & 1;

    int stage = 0;
    for (int k = 0; k < NCHUNK; k++) {
        if (k < NCHUNK - 1) CP_WAIT(1); else CP_WAIT(0);
        __syncthreads();

        const uint32_t st = sbase + stage * STAGE_B;
        const uint32_t aA = st, aB = st + TILE_B;

#pragma unroll
        for (int ks = 0; ks < 4; ks++) {
            uint32_t af[2][4], bf[8][2];
#pragma unroll
            for (int mi = 0; mi < 2; mi++) {
                int row = wm * 32 + mi * 16 + a_roff;
                int c = (ks * 2 + a_half) ^ (row & 7);
                LDSM_X4(af[mi][0], af[mi][1], af[mi][2], af[mi][3],
                        aA + row * 128 + (c << 4));
            }
#pragma unroll
            for (int g = 0; g < 4; g++) {
                int row = wn * 64 + g * 16 + b_roff;
                int c = (ks * 2 + b_half) ^ (row & 7);
                uint32_t r0, r1, r2, r3;
                LDSM_X4(r0, r1, r2, r3, aB + row * 128 + (c << 4));
                bf[g * 2][0] = r0; bf[g * 2][1] = r1;
                bf[g * 2 + 1][0] = r2; bf[g * 2 + 1][1] = r3;
            }
#pragma unroll
            for (int mi = 0; mi < 2; mi++)
#pragma unroll
                for (int ni = 0; ni < 8; ni++)
                    MMA16816(acc[mi][ni], af[mi], bf[ni]);
        }

        if (k + 2 < NCHUNK) {
            int s2 = stage + 2; if (s2 >= 3) s2 -= 3;
            uint32_t stw = sbase + s2 * STAGE_B;
            const int kk = (k + 2) * BKK;
            load_tile(stw + 0 * TILE_B, A, m0, kk);
            load_tile(stw + 1 * TILE_B, Bm, n0, kk);
        }
        CP_COMMIT();
        if (++stage == 3) stage = 0;
    }

    // ----- epilogue -----
    if (U0) {
#pragma unroll
        for (int ni = 0; ni < 8; ni++) {
            int col = n0 + wn * 64 + ni * 8 + (lane & 3) * 2;   // even
#pragma unroll
            for (int mi = 0; mi < 2; mi++) {
                int row = m0 + wm * 32 + mi * 16 + (lane >> 2);
                if (col < D_) {
                    float* p0 = U0 + (size_t)row * D_ + col;
                    float* p1 = U0 + (size_t)(row + 8) * D_ + col;
                    *(float2*)p0 = make_float2(acc[mi][ni][0], acc[mi][ni][1]);
                    *(float2*)p1 = make_float2(acc[mi][ni][2], acc[mi][ni][3]);
                } else {
                    int off;
                    if (col < 2 * D_) off = 2 * (col - D_);          // u1 pair
                    else              off = 2 * (col - 2 * D_) + 2;  // u2 pair
                    __half2* p0 = (__half2*)(U12 + (size_t)row * (2 * D_) + off);
                    __half2* p1 = (__half2*)(U12 + (size_t)(row + 8) * (2 * D_) + off);
                    *p0 = __floats2half2_rn(acc[mi][ni][0], acc[mi][ni][1]);
                    *p1 = __floats2half2_rn(acc[mi][ni][2], acc[mi][ni][3]);
                }
            }
        }
    } else {
        const bool vec = ((ldc & 1) == 0);
#pragma unroll
        for (int ni = 0; ni < 8; ni++) {
            int col = n0 + wn * 64 + ni * 8 + (lane & 3) * 2;
            float bv0 = 0.f, bv1 = 0.f;
            if (bias) {
                if (col < nmax)     bv0 = bias[col];
                if (col + 1 < nmax) bv1 = bias[col + 1];
            }
#pragma unroll
            for (int mi = 0; mi < 2; mi++) {
                int row = m0 + wm * 32 + mi * 16 + (lane >> 2);
                float* p0 = C + (size_t)row * ldc + col;
                float* p1 = C + (size_t)(row + 8) * ldc + col;
                if (vec && col + 1 < nmax) {
                    *(float2*)p0 = make_float2(acc[mi][ni][0] + bv0, acc[mi][ni][1] + bv1);
                    *(float2*)p1 = make_float2(acc[mi][ni][2] + bv0, acc[mi][ni][3] + bv1);
                } else {
                    if (col < nmax) {
                        p0[0] = acc[mi][ni][0] + bv0;
                        p1[0] = acc[mi][ni][2] + bv0;
                    }
                    if (col + 1 < nmax) {
                        p0[1] = acc[mi][ni][1] + bv1;
                        p1[1] = acc[mi][ni][3] + bv1;
                    }
                }
            }
        }
    }
}

// ---------------------------------------------------------------------------
// Layer-0 fused GEMM: U = x16 @ Weff^T + beff.  K=64 (20 real), one chunk.
// Same warp layout + SRU epilogue (R14 layout) with beff bias added.
// SMEM: 2 tiles x 16 KB = 32 KB.
// ---------------------------------------------------------------------------
__global__ __launch_bounds__(256, 2) void gemm0_kernel(
    const __half* __restrict__ X, const __half* __restrict__ Bm,
    const float* __restrict__ beff,
    float* __restrict__ U0, __half* __restrict__ U12)
{
    extern __shared__ char smem[];
    const uint32_t sbase = smem_to_u32(smem);
    const int tid = threadIdx.x;
    const int lane = tid & 31;
    const int wid = tid >> 5;
    const int wm = wid & 3;
    const int wn = wid >> 2;
    const int m0 = blockIdx.y * 128;
    const int n0 = blockIdx.x * 128;

    float acc[2][8][4];
#pragma unroll
    for (int i = 0; i < 2; i++)
#pragma unroll
        for (int j = 0; j < 8; j++)
#pragma unroll
            for (int q = 0; q < 4; q++) acc[i][j][q] = 0.0f;

    load_tile64(sbase + 0 * TILE_B, X, m0);
    load_tile64(sbase + 1 * TILE_B, Bm, n0);
    CP_COMMIT();

    const int a_roff = (lane & 7) + ((lane >> 3) & 1) * 8;
    const int a_half = (lane >> 4) & 1;
    const int b_roff = (lane & 7) + ((lane >> 4) & 1) * 8;
    const int b_half = (lane >> 3) & 1;

    CP_WAIT(0);
    __syncthreads();

    const uint32_t aA = sbase, aB = sbase + TILE_B;
    // only ks=0,1 carry data (K real = 20 < 32); upper half is zero anyway,
    // but skipping ks=2,3 saves work since cols 32..63 are zero padded.
#pragma unroll
    for (int ks = 0; ks < 2; ks++) {
        uint32_t af[2][4], bf[8][2];
#pragma unroll
        for (int mi = 0; mi < 2; mi++) {
            int row = wm * 32 + mi * 16 + a_roff;
            int c = (ks * 2 + a_half) ^ (row & 7);
            LDSM_X4(af[mi][0], af[mi][1], af[mi][2], af[mi][3],
                    aA + row * 128 + (c << 4));
        }
#pragma unroll
        for (int g = 0; g < 4; g++) {
            int row = wn * 64 + g * 16 + b_roff;
            int c = (ks * 2 + b_half) ^ (row & 7);
            uint32_t r0, r1, r2, r3;
            LDSM_X4(r0, r1, r2, r3, aB + row * 128 + (c << 4));
            bf[g * 2][0] = r0; bf[g * 2][1] = r1;
            bf[g * 2 + 1][0] = r2; bf[g * 2 + 1][1] = r3;
        }
#pragma unroll
        for (int mi = 0; mi < 2; mi++)
#pragma unroll
            for (int ni = 0; ni < 8; ni++)
                MMA16816(acc[mi][ni], af[mi], bf[ni]);
    }

    // ----- SRU epilogue with beff bias -----
#pragma unroll
    for (int ni = 0; ni < 8; ni++) {
        int col = n0 + wn * 64 + ni * 8 + (lane & 3) * 2;   // even
        float bv0 = beff[col], bv1 = beff[col + 1];
#pragma unroll
        for (int mi = 0; mi < 2; mi++) {
            int row = m0 + wm * 32 + mi * 16 + (lane >> 2);
            float a0 = acc[mi][ni][0] + bv0, a1 = acc[mi][ni][1] + bv1;
            float a2 = acc[mi][ni][2] + bv0, a3 = acc[mi][ni][3] + bv1;
            if (col < D_) {
                float* p0 = U0 + (size_t)row * D_ + col;
                float* p1 = U0 + (size_t)(row + 8) * D_ + col;
                *(float2*)p0 = make_float2(a0, a1);
                *(float2*)p1 = make_float2(a2, a3);
            } else {
                int off;
                if (col < 2 * D_) off = 2 * (col - D_);
                else              off = 2 * (col - 2 * D_) + 2;
                __half2* p0 = (__half2*)(U12 + (size_t)row * (2 * D_) + off);
                __half2* p1 = (__half2*)(U12 + (size_t)(row + 8) * (2 * D_) + off);
                *p0 = __floats2half2_rn(a0, a1);
                *p1 = __floats2half2_rn(a2, a3);
            }
        }
    }
}

// ---------------------------------------------------------------------------
// SRU recurrence (R14 exact): ONE channel per thread, cp.async ring depth 8,
// t-loop unrolled by 8, pointer-increment streams, 8B u12 pair granule.
// ---------------------------------------------------------------------------
#define SPFD 8
#define STH 512
#define SRU_SMEM (SPFD * STH * 16)   // 65536 bytes

__global__ __launch_bounds__(STH) void sru_kernel(
    const float* __restrict__ U0, const __half* __restrict__ U12,
    __half* __restrict__ A, __half* __restrict__ Aord,
    const float* __restrict__ v, const float* __restrict__ bp,
    float* __restrict__ cfin, int last)
{
    extern __shared__ char ssru[];
    float* s_u0  = (float*)ssru;
    uint2* s_u12 = (uint2*)(ssru + SPFD * STH * 4);
    uint32_t* s_xt = (uint32_t*)(ssru + SPFD * STH * 12);

    const int tid = threadIdx.x;
    int idx = blockIdx.x * STH + tid;
    int b = idx >> 10;
    int d = idx & (D_ - 1);
    int d0 = d & ~1;
    int sub = d & 1;

    const float vf = v[d], vr = v[D_ + d];
    const float bf = bp[d], br = bp[D_ + d];
    float c = 0.0f;

    const size_t u0off  = (size_t)b * D_ + d;
    const size_t xtoff  = (size_t)b * D_ + d0;
    const size_t u12off = (size_t)b * (2 * D_) + 2 * d0;
    const size_t u0step  = (size_t)B_ * D_;
    const size_t u12step = (size_t)B_ * (2 * D_);

    const float*  ldU0  = U0 + u0off + SPFD * u0step;
    const __half* ldU12 = U12 + u12off + SPFD * u12step;
    const __half* ldXt  = A + xtoff + SPFD * u0step;
    __half* pOut = last ? (Aord + (size_t)b * T_ * D_ + d) : (A + u0off);
    const size_t outstep = last ? (size_t)D_ : u0step;

    const uint32_t su0  = smem_to_u32(&s_u0[tid]);
    const uint32_t su12 = smem_to_u32(&s_u12[tid]);
    const uint32_t sxt  = smem_to_u32(&s_xt[tid]);

#pragma unroll
    for (int p = 0; p < SPFD; p++) {
        CP_ASYNC4(su0  + p * STH * 4, U0 + u0off + (size_t)p * u0step);
        CP_ASYNC8(su12 + p * STH * 8, U12 + u12off + (size_t)p * u12step);
        CP_ASYNC4(sxt  + p * STH * 4, A + xtoff + (size_t)p * u0step);
        CP_COMMIT();
    }

    for (int t0 = 0; t0 < T_; t0 += SPFD) {
#pragma unroll
        for (int j = 0; j < SPFD; j++) {
            CP_WAIT(7);

            float u0v = s_u0[j * STH + tid];
            uint2 w12 = s_u12[j * STH + tid];
            float2 u1p = __half22float2(*(__half2*)&w12.x);
            float2 u2p = __half22float2(*(__half2*)&w12.y);
            float u1 = sub ? u1p.y : u1p.x;
            float u2 = sub ? u2p.y : u2p.x;
            uint32_t xw = s_xt[j * STH + tid];
            float2 xp = __half22float2(*(__half2*)&xw);
            float xt = sub ? xp.y : xp.x;

            if (t0 + j + SPFD < T_) {
                CP_ASYNC4(su0  + j * STH * 4, ldU0);
                CP_ASYNC8(su12 + j * STH * 8, ldU12);
                CP_ASYNC4(sxt  + j * STH * 4, ldXt);
            }
            ldU0 += u0step; ldU12 += u12step; ldXt += u0step;
            CP_COMMIT();

            float f = 1.0f / (1.0f + __expf(-(u1 + vf * c + bf)));
            c = f * c + (1.0f - f) * u0v;
            float r = 1.0f / (1.0f + __expf(-(u2 + vr * c + br)));
            float h = r * c + (1.0f - r) * xt;

            *pOut = __float2half(h);
            pOut += outstep;
        }
    }
    cfin[u0off] = c;
}

// ---------------------------------------------------------------------------
// Launcher
// ---------------------------------------------------------------------------
extern "C" void kernel_launch(void* const* d_in, const int* in_sizes, int n_in,
                              void* d_out, int out_size)
{
    const float* x     = (const float*)d_in[0];
    const float* W1    = (const float*)d_in[2];
    const float* b1    = (const float*)d_in[3];
    const float* sru_W = (const float*)d_in[4];
    const float* sru_v = (const float*)d_in[5];
    const float* sru_b = (const float*)d_in[6];
    const float* W3    = (const float*)d_in[7];
    const float* b3    = (const float*)d_in[8];
    float* out = (float*)d_out;

    float *U0P, *beffP;
    __half *U12P, *AP, *AordP, *WtP, *W3tP, *X16P, *WeffP;
    cudaGetSymbolAddress((void**)&U0P, g_U0);
    cudaGetSymbolAddress((void**)&U12P, g_U12);
    cudaGetSymbolAddress((void**)&AP, g_A);
    cudaGetSymbolAddress((void**)&AordP, g_Aord);
    cudaGetSymbolAddress((void**)&WtP, g_Wt);
    cudaGetSymbolAddress((void**)&W3tP, g_W3t);
    cudaGetSymbolAddress((void**)&X16P, g_X16);
    cudaGetSymbolAddress((void**)&WeffP, g_Weff);
    cudaGetSymbolAddress((void**)&beffP, g_beff);

    cudaFuncSetAttribute(gemm_kernel, cudaFuncAttributeMaxDynamicSharedMemorySize, GEMM_SMEM);
    cudaFuncSetAttribute(sru_kernel, cudaFuncAttributeMaxDynamicSharedMemorySize, SRU_SMEM);

    // Weight prep (merged: 3 SRU layers + W3), then W_eff (needs g_Wt[0])
    {
        dim3 g(N3_ / 32, D_ / 32, L_ + 1);
        wprep_kernel<<<g, 256>>>(sru_W, W3);
        weff_kernel<<<N3_, 32>>>(W1, b1);
    }

    // Input projection (h0 for xt, and padded x16)
    proj_kernel<<<M_ / PROJ_ROWS, 256>>>(x, W1, b1);

    // Layer 0: fused K=20 GEMM
    {
        dim3 grid(N3_ / 128, M_ / 128);
        gemm0_kernel<<<grid, 256, STAGE_B>>>(X16P, WeffP, beffP, U0P, U12P);
        const float* vl = sru_v;
        const float* bl = sru_b;
        float* cfin = out + Y_SIZE;
        sru_kernel<<<(B_ * D_) / STH, STH, SRU_SMEM>>>(U0P, U12P, AP, AordP, vl, bl, cfin, 0);
    }

    // Layers 1..2
    for (int l = 1; l < L_; l++) {
        const __half* Bh = WtP + (size_t)l * N3_ * D_;
        dim3 grid(N3_ / 128, M_ / 128);
        gemm_kernel<<<grid, 256, GEMM_SMEM>>>(AP, Bh, nullptr, 0, 0, nullptr, U0P, U12P);

        const float* vl = sru_v + (size_t)l * 2 * D_;
        const float* bl = sru_b + (size_t)l * 2 * D_;
        float* cfin = out + Y_SIZE + (size_t)l * B_ * D_;
        int last = (l == L_ - 1) ? 1 : 0;
        sru_kernel<<<(B_ * D_) / STH, STH, SRU_SMEM>>>(U0P, U12P, AP, AordP, vl, bl, cfin, last);
    }

    // Output GEMM: y = h @ W3 + b3
    {
        dim3 grid(OPAD / 128, M_ / 128);
        gemm_kernel<<<grid, 256, GEMM_SMEM>>>(AordP, W3tP, out, O_, O_, b3, nullptr, nullptr);
    }
}

// round 17
// speedup vs baseline: 1.3372x; 1.1462x over previous
#include <cuda_runtime.h>
#include <cuda_fp16.h>
#include <cstdint>
#include <math.h>

// Problem dims
#define B_  64
#define T_  512
#define F_  20
#define D_  1024
#define O_  1095
#define L_  3
#define M_  (B_ * T_)        // 32768
#define N3_ (3 * D_)         // 3072
#define OPAD 1152
#define KP0 64               // padded K for the fused layer-0 GEMM
#define Y_SIZE ((size_t)M_ * O_)

// ---------------------------------------------------------------------------
// Scratch (static device globals)
// ---------------------------------------------------------------------------
__device__ float  g_U0[(size_t)M_ * D_];          // u0 gate pre-activation (fp32)
__device__ __half g_U12[(size_t)M_ * 2 * D_];     // pair-interleaved (R14 layout)
__device__ __half g_A[(size_t)M_ * D_];           // fp16 hidden (time-major)
__device__ __half g_Aord[(size_t)M_ * D_];        // fp16 hidden (batch-major, last layer)
__device__ __half g_Wt[(size_t)L_ * N3_ * D_];    // sru_W^T fp16  [l][n][k]
__device__ __half g_W3t[(size_t)OPAD * D_];       // W3^T fp16 (zero padded)
__device__ __half g_X16[(size_t)M_ * KP0];        // fp16 x, time-major, K padded 20->64
__device__ __half g_Weff[(size_t)N3_ * KP0];      // (W1 @ W0)^T fp16, [n][k], zero pad
__device__ float  g_beff[N3_];                    // b1 @ W0 (fp32)

__device__ __forceinline__ uint32_t smem_to_u32(const void* p) {
    uint32_t a;
    asm("{ .reg .u64 t; cvta.to.shared.u64 t, %1; cvt.u32.u64 %0, t; }" : "=r"(a) : "l"(p));
    return a;
}

// ---------------------------------------------------------------------------
// Input projection -> g_A (fp16, time-major) AND g_X16 (fp16 x rows, padded)
// ---------------------------------------------------------------------------
#define PROJ_ROWS 16
__global__ __launch_bounds__(256) void proj_kernel(
    const float* __restrict__ x, const float* __restrict__ W1,
    const float* __restrict__ b1)
{
    int r0 = blockIdx.x * PROJ_ROWS;
    __shared__ float xs[PROJ_ROWS][F_];
    for (int i = threadIdx.x; i < PROJ_ROWS * F_; i += blockDim.x) {
        int rr = i / F_, f = i % F_;
        int r = r0 + rr;
        int b = r % B_, t = r / B_;
        xs[rr][f] = x[((size_t)b * T_ + t) * F_ + f];
    }
    __syncthreads();
    for (int i = threadIdx.x; i < PROJ_ROWS * KP0; i += blockDim.x) {
        int rr = i / KP0, f = i % KP0;
        g_X16[(size_t)(r0 + rr) * KP0 + f] =
            __float2half(f < F_ ? xs[rr][f] : 0.0f);
    }
    for (int d = threadIdx.x; d < D_; d += blockDim.x) {
        float w[F_];
#pragma unroll
        for (int f = 0; f < F_; f++) w[f] = W1[f * D_ + d];
        float bb = b1[d];
#pragma unroll
        for (int rr = 0; rr < PROJ_ROWS; rr++) {
            float acc = bb;
#pragma unroll
            for (int f = 0; f < F_; f++) acc += xs[rr][f] * w[f];
            g_A[(size_t)(r0 + rr) * D_ + d] = __float2half(acc);
        }
    }
}

// ---------------------------------------------------------------------------
// Weight prep (merged): z<L -> sru layer z; z==L -> W3 (zero padded)
// ---------------------------------------------------------------------------
__global__ __launch_bounds__(256) void wprep_kernel(
    const float* __restrict__ W, const float* __restrict__ W3)
{
    __shared__ float tile[32][33];
    int z = blockIdx.z;
    int n0 = blockIdx.x * 32, k0 = blockIdx.y * 32;
    int tx = threadIdx.x & 31, ty = threadIdx.x >> 5;

    if (z < L_) {
        const float* Wl = W + (size_t)z * D_ * N3_;
        for (int dy = ty; dy < 32; dy += 8)
            tile[dy][tx] = Wl[(size_t)(k0 + dy) * N3_ + n0 + tx];
        __syncthreads();
        __half* oh = g_Wt + (size_t)z * N3_ * D_;
        for (int dy = ty; dy < 32; dy += 8)
            oh[(size_t)(n0 + dy) * D_ + k0 + tx] = __float2half(tile[tx][dy]);
    } else {
        if (n0 >= OPAD) return;
        for (int dy = ty; dy < 32; dy += 8) {
            int n = n0 + tx;
            tile[dy][tx] = (n < O_) ? W3[(size_t)(k0 + dy) * O_ + n] : 0.0f;
        }
        __syncthreads();
        for (int dy = ty; dy < 32; dy += 8)
            g_W3t[(size_t)(n0 + dy) * D_ + k0 + tx] = __float2half(tile[tx][dy]);
    }
}

// ---------------------------------------------------------------------------
// W_eff prep (parallel): one block per n; warp w handles rows w, w+8, w+16
// of the 21 reductions (20 W1 rows + b1) over d=0..1023; shfl reduce.
// ---------------------------------------------------------------------------
__global__ __launch_bounds__(256) void weff_kernel(
    const float* __restrict__ W1, const float* __restrict__ b1)
{
    int n = blockIdx.x;
    const __half* wt0 = g_Wt + (size_t)n * D_;
    int lane = threadIdx.x & 31, w = threadIdx.x >> 5;

    for (int r = w; r < F_ + 1; r += 8) {
        const float* src = (r < F_) ? (W1 + (size_t)r * D_) : b1;
        float acc = 0.0f;
        for (int d = lane; d < D_; d += 32)
            acc += src[d] * __half2float(wt0[d]);
#pragma unroll
        for (int o = 16; o; o >>= 1)
            acc += __shfl_down_sync(0xffffffffu, acc, o);
        if (lane == 0) {
            if (r < F_) g_Weff[(size_t)n * KP0 + r] = __float2half(acc);
            else        g_beff[n] = acc;
        }
    }
    int k = threadIdx.x;
    if (k >= F_ && k < KP0)
        g_Weff[(size_t)n * KP0 + k] = __float2half(0.0f);
}

// ---------------------------------------------------------------------------
// mma.sync fp16 GEMM. BK=64, 3-stage cp.async pipeline, ONE sync per k-iter.
// SRU mode (U0 != null): u0 -> fp32 U0; u1/u2 -> pair-interleaved fp16 U12.
// (R14-measured configuration — unchanged.)
// ---------------------------------------------------------------------------
#define BKK 64
#define NCHUNK (D_ / BKK)        // 16
#define TILE_B (128 * 128)       // 16384 bytes per tile
#define STAGE_B (2 * TILE_B)     // 32768 (A + B)
#define GEMM_SMEM (3 * STAGE_B)  // 98304

#define CP_ASYNC16(s, g) \
    asm volatile("cp.async.cg.shared.global [%0], [%1], 16;" :: "r"(s), "l"(g))
#define CP_ASYNC8(s, g) \
    asm volatile("cp.async.ca.shared.global [%0], [%1], 8;" :: "r"(s), "l"(g))
#define CP_ASYNC4(s, g) \
    asm volatile("cp.async.ca.shared.global [%0], [%1], 4;" :: "r"(s), "l"(g))
#define CP_COMMIT() asm volatile("cp.async.commit_group;" ::: "memory")
#define CP_WAIT(n)  asm volatile("cp.async.wait_group %0;" :: "n"(n) : "memory")

#define LDSM_X4(r0, r1, r2, r3, a) \
    asm volatile("ldmatrix.sync.aligned.m8n8.x4.shared.b16 {%0,%1,%2,%3}, [%4];" \
        : "=r"(r0), "=r"(r1), "=r"(r2), "=r"(r3) : "r"(a))

#define MMA16816(c, a, b) \
    asm volatile("mma.sync.aligned.m16n8k16.row.col.f32.f16.f16.f32 " \
        "{%0,%1,%2,%3}, {%4,%5,%6,%7}, {%8,%9}, {%0,%1,%2,%3};" \
        : "+f"((c)[0]), "+f"((c)[1]), "+f"((c)[2]), "+f"((c)[3]) \
        : "r"((a)[0]), "r"((a)[1]), "r"((a)[2]), "r"((a)[3]), "r"((b)[0]), "r"((b)[1]))

__device__ __forceinline__ void load_tile(uint32_t sbase, const __half* g,
                                          int row0, int kk) {
    const int tid = threadIdx.x;
#pragma unroll
    for (int j = 0; j < 4; j++) {
        int i = tid + 256 * j;         // 0..1023
        int row = i >> 3;
        int c = i & 7;
        uint32_t s = sbase + row * 128 + ((c ^ (row & 7)) << 4);
        const void* gp = g + (size_t)(row0 + row) * D_ + kk + c * 8;
        CP_ASYNC16(s, gp);
    }
}

__device__ __forceinline__ void load_tile64(uint32_t sbase, const __half* g,
                                            int row0) {
    const int tid = threadIdx.x;
#pragma unroll
    for (int j = 0; j < 4; j++) {
        int i = tid + 256 * j;
        int row = i >> 3;
        int c = i & 7;
        uint32_t s = sbase + row * 128 + ((c ^ (row & 7)) << 4);
        const void* gp = g + (size_t)(row0 + row) * KP0 + c * 8;
        CP_ASYNC16(s, gp);
    }
}

__global__ __launch_bounds__(256, 2) void gemm_kernel(
    const __half* __restrict__ A, const __half* __restrict__ Bm,
    float* __restrict__ C, int ldc, int nmax, const float* __restrict__ bias,
    float* __restrict__ U0, __half* __restrict__ U12)
{
    extern __shared__ char smem[];
    const uint32_t sbase = smem_to_u32(smem);
    const int tid = threadIdx.x;
    const int lane = tid & 31;
    const int wid = tid >> 5;
    const int wm = wid & 3;
    const int wn = wid >> 2;
    const int m0 = blockIdx.y * 128;
    const int n0 = blockIdx.x * 128;

    float acc[2][8][4];
#pragma unroll
    for (int i = 0; i < 2; i++)
#pragma unroll
        for (int j = 0; j < 8; j++)
#pragma unroll
            for (int q = 0; q < 4; q++) acc[i][j][q] = 0.0f;

#pragma unroll
    for (int p = 0; p < 2; p++) {
        uint32_t st = sbase + p * STAGE_B;
        load_tile(st + 0 * TILE_B, A, m0, p * BKK);
        load_tile(st + 1 * TILE_B, Bm, n0, p * BKK);
        CP_COMMIT();
    }

    const int a_roff = (lane & 7) + ((lane >> 3) & 1) * 8;
    const int a_half = (lane >> 4) & 1;
    const int b_roff = (lane & 7) + ((lane >> 4) & 1) * 8;
    const int b_half = (lane >> 3) & 1;

    int stage = 0;
    for (int k = 0; k < NCHUNK; k++) {
        if (k < NCHUNK - 1) CP_WAIT(1); else CP_WAIT(0);
        __syncthreads();

        const uint32_t st = sbase + stage * STAGE_B;
        const uint32_t aA = st, aB = st + TILE_B;

#pragma unroll
        for (int ks = 0; ks < 4; ks++) {
            uint32_t af[2][4], bf[8][2];
#pragma unroll
            for (int mi = 0; mi < 2; mi++) {
                int row = wm * 32 + mi * 16 + a_roff;
                int c = (ks * 2 + a_half) ^ (row & 7);
                LDSM_X4(af[mi][0], af[mi][1], af[mi][2], af[mi][3],
                        aA + row * 128 + (c << 4));
            }
#pragma unroll
            for (int g = 0; g < 4; g++) {
                int row = wn * 64 + g * 16 + b_roff;
                int c = (ks * 2 + b_half) ^ (row & 7);
                uint32_t r0, r1, r2, r3;
                LDSM_X4(r0, r1, r2, r3, aB + row * 128 + (c << 4));
                bf[g * 2][0] = r0; bf[g * 2][1] = r1;
                bf[g * 2 + 1][0] = r2; bf[g * 2 + 1][1] = r3;
            }
#pragma unroll
            for (int mi = 0; mi < 2; mi++)
#pragma unroll
                for (int ni = 0; ni < 8; ni++)
                    MMA16816(acc[mi][ni], af[mi], bf[ni]);
        }

        if (k + 2 < NCHUNK) {
            int s2 = stage + 2; if (s2 >= 3) s2 -= 3;
            uint32_t stw = sbase + s2 * STAGE_B;
            const int kk = (k + 2) * BKK;
            load_tile(stw + 0 * TILE_B, A, m0, kk);
            load_tile(stw + 1 * TILE_B, Bm, n0, kk);
        }
        CP_COMMIT();
        if (++stage == 3) stage = 0;
    }

    // ----- epilogue -----
    if (U0) {
#pragma unroll
        for (int ni = 0; ni < 8; ni++) {
            int col = n0 + wn * 64 + ni * 8 + (lane & 3) * 2;   // even
#pragma unroll
            for (int mi = 0; mi < 2; mi++) {
                int row = m0 + wm * 32 + mi * 16 + (lane >> 2);
                if (col < D_) {
                    float* p0 = U0 + (size_t)row * D_ + col;
                    float* p1 = U0 + (size_t)(row + 8) * D_ + col;
                    *(float2*)p0 = make_float2(acc[mi][ni][0], acc[mi][ni][1]);
                    *(float2*)p1 = make_float2(acc[mi][ni][2], acc[mi][ni][3]);
                } else {
                    int off;
                    if (col < 2 * D_) off = 2 * (col - D_);          // u1 pair
                    else              off = 2 * (col - 2 * D_) + 2;  // u2 pair
                    __half2* p0 = (__half2*)(U12 + (size_t)row * (2 * D_) + off);
                    __half2* p1 = (__half2*)(U12 + (size_t)(row + 8) * (2 * D_) + off);
                    *p0 = __floats2half2_rn(acc[mi][ni][0], acc[mi][ni][1]);
                    *p1 = __floats2half2_rn(acc[mi][ni][2], acc[mi][ni][3]);
                }
            }
        }
    } else {
        const bool vec = ((ldc & 1) == 0);
#pragma unroll
        for (int ni = 0; ni < 8; ni++) {
            int col = n0 + wn * 64 + ni * 8 + (lane & 3) * 2;
            float bv0 = 0.f, bv1 = 0.f;
            if (bias) {
                if (col < nmax)     bv0 = bias[col];
                if (col + 1 < nmax) bv1 = bias[col + 1];
            }
#pragma unroll
            for (int mi = 0; mi < 2; mi++) {
                int row = m0 + wm * 32 + mi * 16 + (lane >> 2);
                float* p0 = C + (size_t)row * ldc + col;
                float* p1 = C + (size_t)(row + 8) * ldc + col;
                if (vec && col + 1 < nmax) {
                    *(float2*)p0 = make_float2(acc[mi][ni][0] + bv0, acc[mi][ni][1] + bv1);
                    *(float2*)p1 = make_float2(acc[mi][ni][2] + bv0, acc[mi][ni][3] + bv1);
                } else {
                    if (col < nmax) {
                        p0[0] = acc[mi][ni][0] + bv0;
                        p1[0] = acc[mi][ni][2] + bv0;
                    }
                    if (col + 1 < nmax) {
                        p0[1] = acc[mi][ni][1] + bv1;
                        p1[1] = acc[mi][ni][3] + bv1;
                    }
                }
            }
        }
    }
}

// ---------------------------------------------------------------------------
// Layer-0 fused GEMM: U = x16 @ Weff^T + beff.  K=64 (20 real), one chunk.
// ---------------------------------------------------------------------------
__global__ __launch_bounds__(256, 2) void gemm0_kernel(
    const __half* __restrict__ X, const __half* __restrict__ Bm,
    const float* __restrict__ beff,
    float* __restrict__ U0, __half* __restrict__ U12)
{
    extern __shared__ char smem[];
    const uint32_t sbase = smem_to_u32(smem);
    const int tid = threadIdx.x;
    const int lane = tid & 31;
    const int wid = tid >> 5;
    const int wm = wid & 3;
    const int wn = wid >> 2;
    const int m0 = blockIdx.y * 128;
    const int n0 = blockIdx.x * 128;

    float acc[2][8][4];
#pragma unroll
    for (int i = 0; i < 2; i++)
#pragma unroll
        for (int j = 0; j < 8; j++)
#pragma unroll
            for (int q = 0; q < 4; q++) acc[i][j][q] = 0.0f;

    load_tile64(sbase + 0 * TILE_B, X, m0);
    load_tile64(sbase + 1 * TILE_B, Bm, n0);
    CP_COMMIT();

    const int a_roff = (lane & 7) + ((lane >> 3) & 1) * 8;
    const int a_half = (lane >> 4) & 1;
    const int b_roff = (lane & 7) + ((lane >> 4) & 1) * 8;
    const int b_half = (lane >> 3) & 1;

    CP_WAIT(0);
    __syncthreads();

    const uint32_t aA = sbase, aB = sbase + TILE_B;
#pragma unroll
    for (int ks = 0; ks < 2; ks++) {
        uint32_t af[2][4], bf[8][2];
#pragma unroll
        for (int mi = 0; mi < 2; mi++) {
            int row = wm * 32 + mi * 16 + a_roff;
            int c = (ks * 2 + a_half) ^ (row & 7);
            LDSM_X4(af[mi][0], af[mi][1], af[mi][2], af[mi][3],
                    aA + row * 128 + (c << 4));
        }
#pragma unroll
        for (int g = 0; g < 4; g++) {
            int row = wn * 64 + g * 16 + b_roff;
            int c = (ks * 2 + b_half) ^ (row & 7);
            uint32_t r0, r1, r2, r3;
            LDSM_X4(r0, r1, r2, r3, aB + row * 128 + (c << 4));
            bf[g * 2][0] = r0; bf[g * 2][1] = r1;
            bf[g * 2 + 1][0] = r2; bf[g * 2 + 1][1] = r3;
        }
#pragma unroll
        for (int mi = 0; mi < 2; mi++)
#pragma unroll
            for (int ni = 0; ni < 8; ni++)
                MMA16816(acc[mi][ni], af[mi], bf[ni]);
    }

#pragma unroll
    for (int ni = 0; ni < 8; ni++) {
        int col = n0 + wn * 64 + ni * 8 + (lane & 3) * 2;   // even
        float bv0 = beff[col], bv1 = beff[col + 1];
#pragma unroll
        for (int mi = 0; mi < 2; mi++) {
            int row = m0 + wm * 32 + mi * 16 + (lane >> 2);
            float a0 = acc[mi][ni][0] + bv0, a1 = acc[mi][ni][1] + bv1;
            float a2 = acc[mi][ni][2] + bv0, a3 = acc[mi][ni][3] + bv1;
            if (col < D_) {
                float* p0 = U0 + (size_t)row * D_ + col;
                float* p1 = U0 + (size_t)(row + 8) * D_ + col;
                *(float2*)p0 = make_float2(a0, a1);
                *(float2*)p1 = make_float2(a2, a3);
            } else {
                int off;
                if (col < 2 * D_) off = 2 * (col - D_);
                else              off = 2 * (col - 2 * D_) + 2;
                __half2* p0 = (__half2*)(U12 + (size_t)row * (2 * D_) + off);
                __half2* p1 = (__half2*)(U12 + (size_t)(row + 8) * (2 * D_) + off);
                *p0 = __floats2half2_rn(a0, a1);
                *p1 = __floats2half2_rn(a2, a3);
            }
        }
    }
}

// ---------------------------------------------------------------------------
// SRU recurrence: ONE channel per thread, cp.async ring depth 16 in
// commit-groups of 4 stages (one wait + one commit per 4 timesteps).
// Pointer increments per group; q*step offsets fold into LDGSTS immediates.
// 128 CTAs x 512 threads (1 CTA/SM). Dynamic smem: 16 x 512 x 16 = 128 KB.
// ---------------------------------------------------------------------------
#define SPFD 16     // ring depth; T_ % SPFD == 0
#define SGRP 4      // stages per commit group
#define STH 512
#define SRU_SMEM (SPFD * STH * 16)   // 131072 bytes

__global__ __launch_bounds__(STH) void sru_kernel(
    const float* __restrict__ U0, const __half* __restrict__ U12,
    __half* __restrict__ A, __half* __restrict__ Aord,
    const float* __restrict__ v, const float* __restrict__ bp,
    float* __restrict__ cfin, int last)
{
    extern __shared__ char ssru[];
    float* s_u0  = (float*)ssru;                          // [SPFD][STH] 32 KB
    uint2* s_u12 = (uint2*)(ssru + SPFD * STH * 4);       // [SPFD][STH] 64 KB
    uint32_t* s_xt = (uint32_t*)(ssru + SPFD * STH * 12); // [SPFD][STH] 32 KB

    const int tid = threadIdx.x;
    int idx = blockIdx.x * STH + tid;
    int b = idx >> 10;
    int d = idx & (D_ - 1);
    int d0 = d & ~1;
    int sub = d & 1;

    const float vf = v[d], vr = v[D_ + d];
    const float bf = bp[d], br = bp[D_ + d];
    float c = 0.0f;

    const size_t u0off  = (size_t)b * D_ + d;
    const size_t xtoff  = (size_t)b * D_ + d0;
    const size_t u12off = (size_t)b * (2 * D_) + 2 * d0;
    const size_t u0step  = (size_t)B_ * D_;
    const size_t u12step = (size_t)B_ * (2 * D_);

    // group-stepped pointers (refill source for stage t+SPFD)
    const float*  ldU0  = U0 + u0off + SPFD * u0step;
    const __half* ldU12 = U12 + u12off + SPFD * u12step;
    const __half* ldXt  = A + xtoff + SPFD * u0step;
    __half* pOut = last ? (Aord + (size_t)b * T_ * D_ + d) : (A + u0off);
    const size_t outstep = last ? (size_t)D_ : u0step;

    const uint32_t su0  = smem_to_u32(&s_u0[tid]);
    const uint32_t su12 = smem_to_u32(&s_u12[tid]);
    const uint32_t sxt  = smem_to_u32(&s_xt[tid]);

    // prologue: 4 commit groups x 4 stages
#pragma unroll
    for (int g = 0; g < SPFD / SGRP; g++) {
#pragma unroll
        for (int q = 0; q < SGRP; q++) {
            int p = g * SGRP + q;
            CP_ASYNC4(su0  + p * STH * 4, U0 + u0off + (size_t)p * u0step);
            CP_ASYNC8(su12 + p * STH * 8, U12 + u12off + (size_t)p * u12step);
            CP_ASYNC4(sxt  + p * STH * 4, A + xtoff + (size_t)p * u0step);
        }
        CP_COMMIT();
    }

    for (int t0 = 0; t0 < T_; t0 += SPFD) {
#pragma unroll
        for (int g = 0; g < SPFD / SGRP; g++) {
            CP_WAIT(3);   // oldest group (stages t0+4g .. t0+4g+3) complete
            const bool pre = (t0 + g * SGRP + SPFD < T_);
#pragma unroll
            for (int q = 0; q < SGRP; q++) {
                const int slot = g * SGRP + q;
                float u0v = s_u0[slot * STH + tid];
                uint2 w12 = s_u12[slot * STH + tid];
                float2 u1p = __half22float2(*(__half2*)&w12.x);
                float2 u2p = __half22float2(*(__half2*)&w12.y);
                float u1 = sub ? u1p.y : u1p.x;
                float u2 = sub ? u2p.y : u2p.x;
                uint32_t xw = s_xt[slot * STH + tid];
                float2 xp = __half22float2(*(__half2*)&xw);
                float xt = sub ? xp.y : xp.x;

                if (pre) {
                    CP_ASYNC4(su0  + slot * STH * 4, ldU0 + q * u0step);
                    CP_ASYNC8(su12 + slot * STH * 8, ldU12 + q * u12step);
                    CP_ASYNC4(sxt  + slot * STH * 4, ldXt + q * u0step);
                }

                float f = 1.0f / (1.0f + __expf(-(u1 + vf * c + bf)));
                c = f * c + (1.0f - f) * u0v;
                float r = 1.0f / (1.0f + __expf(-(u2 + vr * c + br)));
                float h = r * c + (1.0f - r) * xt;

                *pOut = __float2half(h);
                pOut += outstep;
            }
            ldU0 += SGRP * u0step; ldU12 += SGRP * u12step; ldXt += SGRP * u0step;
            CP_COMMIT();
        }
    }
    cfin[u0off] = c;
}

// ---------------------------------------------------------------------------
// Launcher
// ---------------------------------------------------------------------------
extern "C" void kernel_launch(void* const* d_in, const int* in_sizes, int n_in,
                              void* d_out, int out_size)
{
    const float* x     = (const float*)d_in[0];
    const float* W1    = (const float*)d_in[2];
    const float* b1    = (const float*)d_in[3];
    const float* sru_W = (const float*)d_in[4];
    const float* sru_v = (const float*)d_in[5];
    const float* sru_b = (const float*)d_in[6];
    const float* W3    = (const float*)d_in[7];
    const float* b3    = (const float*)d_in[8];
    float* out = (float*)d_out;

    float *U0P, *beffP;
    __half *U12P, *AP, *AordP, *WtP, *W3tP, *X16P, *WeffP;
    cudaGetSymbolAddress((void**)&U0P, g_U0);
    cudaGetSymbolAddress((void**)&U12P, g_U12);
    cudaGetSymbolAddress((void**)&AP, g_A);
    cudaGetSymbolAddress((void**)&AordP, g_Aord);
    cudaGetSymbolAddress((void**)&WtP, g_Wt);
    cudaGetSymbolAddress((void**)&W3tP, g_W3t);
    cudaGetSymbolAddress((void**)&X16P, g_X16);
    cudaGetSymbolAddress((void**)&WeffP, g_Weff);
    cudaGetSymbolAddress((void**)&beffP, g_beff);

    cudaFuncSetAttribute(gemm_kernel, cudaFuncAttributeMaxDynamicSharedMemorySize, GEMM_SMEM);
    cudaFuncSetAttribute(sru_kernel, cudaFuncAttributeMaxDynamicSharedMemorySize, SRU_SMEM);

    // Weight prep (merged: 3 SRU layers + W3), then W_eff (needs g_Wt[0])
    {
        dim3 g(N3_ / 32, D_ / 32, L_ + 1);
        wprep_kernel<<<g, 256>>>(sru_W, W3);
        weff_kernel<<<N3_, 256>>>(W1, b1);
    }

    // Input projection (h0 for xt, and padded x16)
    proj_kernel<<<M_ / PROJ_ROWS, 256>>>(x, W1, b1);

    // Layer 0: fused K=20 GEMM
    {
        dim3 grid(N3_ / 128, M_ / 128);
        gemm0_kernel<<<grid, 256, STAGE_B>>>(X16P, WeffP, beffP, U0P, U12P);
        sru_kernel<<<(B_ * D_) / STH, STH, SRU_SMEM>>>(U0P, U12P, AP, AordP,
                                                       sru_v, sru_b,
                                                       out + Y_SIZE, 0);
    }

    // Layers 1..2
    for (int l = 1; l < L_; l++) {
        const __half* Bh = WtP + (size_t)l * N3_ * D_;
        dim3 grid(N3_ / 128, M_ / 128);
        gemm_kernel<<<grid, 256, GEMM_SMEM>>>(AP, Bh, nullptr, 0, 0, nullptr, U0P, U12P);

        const float* vl = sru_v + (size_t)l * 2 * D_;
        const float* bl = sru_b + (size_t)l * 2 * D_;
        float* cfin = out + Y_SIZE + (size_t)l * B_ * D_;
        int last = (l == L_ - 1) ? 1 : 0;
        sru_kernel<<<(B_ * D_) / STH, STH, SRU_SMEM>>>(U0P, U12P, AP, AordP, vl, bl, cfin, last);
    }

    // Output GEMM: y = h @ W3 + b3
    {
        dim3 grid(OPAD / 128, M_ / 128);
        gemm_kernel<<<grid, 256, GEMM_SMEM>>>(AordP, W3tP, out, O_, O_, b3, nullptr, nullptr);
    }
}